// round 5
// baseline (speedup 1.0000x reference)
#include <cuda_runtime.h>
#include <cuda_bf16.h>
#include <cstdint>

// Problem constants
#define B_      16
#define N_      8192
#define C_      6
#define K_      512      // NUM_GROUP
#define GS_     32       // GROUP_SIZE
#define BIGF    10000000000.0f

// Output layout (float32, concatenated): neighborhood | center | nn_idx
#define NEIGH_ELEMS   (B_*K_*GS_*C_)   // 1,572,864
#define CENTER_ELEMS  (B_*K_*C_)       // 49,152
#define CENTER_OFF    (NEIGH_ELEMS)
#define NN_OFF        (NEIGH_ELEMS + CENTER_ELEMS)

typedef unsigned long long ull;

// Scratch (device globals; no allocation allowed)
__device__ int g_rep[B_ * K_];
__device__ __align__(16) float g_x[B_ * N_];
__device__ __align__(16) float g_y[B_ * N_];
__device__ __align__(16) float g_z[B_ * N_];
__device__ __align__(16) float g_tt[B_ * N_];

// Packed f32x2 ops (Blackwell sm_100+). Per-lane ops are exact rn fp32.
#define ADD2(o,a,b)   asm("add.rn.f32x2 %0, %1, %2;" : "=l"(o) : "l"(a), "l"(b))
#define MUL2(o,a,b)   asm("mul.rn.f32x2 %0, %1, %2;" : "=l"(o) : "l"(a), "l"(b))
#define FMA2(o,a,b,c) asm("fma.rn.f32x2 %0, %1, %2, %3;" : "=l"(o) : "l"(a), "l"(b), "l"(c))

__device__ __forceinline__ ull pk2(float lo, float hi) {
    return (ull)__float_as_uint(lo) | ((ull)__float_as_uint(hi) << 32);
}
__device__ __forceinline__ float plo(ull v) { return __uint_as_float((unsigned)v); }
__device__ __forceinline__ float phi(ull v) { return __uint_as_float((unsigned)(v >> 32)); }

// ---------------------------------------------------------------------------
// Kernel 0: AoS (stride 6) -> SoA xyz + precomputed |t|^2 (exact rn chain).
// ---------------------------------------------------------------------------
__global__ void prep_kernel(const float* __restrict__ pc)
{
    int j = blockIdx.x * 256 + threadIdx.x;
    if (j >= B_ * N_) return;
    const float* p = pc + (size_t)j * C_;
    float px = p[0], py = p[1], pz = p[2];
    g_x[j] = px; g_y[j] = py; g_z[j] = pz;
    g_tt[j] = __fadd_rn(__fadd_rn(__fmul_rn(px, px), __fmul_rn(py, py)),
                        __fmul_rn(pz, pz));
}

// ---------------------------------------------------------------------------
// Kernel 1: Farthest Point Sampling. One CTA/batch, 512 threads, 16 pts/thread
// in registers (f32x2 packed pairs). Reference numerics: d = ((dx^2+dy^2)+dz^2)
// with rn ops (x + (-q) == x - q exactly); dists = min; argmax first-index.
// ONE barrier/iter: per-warp (bits,idx) candidates double-buffered by parity;
// winner coords re-fetched by every thread via same-address LDG (L1-resident).
// In-loop tracking is fminf/fmaxf only; the winning lane recovers its first
// matching slot by an exact post-scan (ties resolved by redux-min on index).
// Distances are sums of squares >= +0, so u32 bit compare == float compare.
// ---------------------------------------------------------------------------
__global__ __launch_bounds__(512, 1)
void fps_kernel(int* __restrict__ rep)
{
    const int b = blockIdx.x, t = threadIdx.x;
    const int lane = t & 31, w = t >> 5;
    const int base = b * N_;

    float xs[16], ys[16], zs[16];
#pragma unroll
    for (int i = 0; i < 16; i++) {
        int j = base + t + i * 512;
        xs[i] = g_x[j]; ys[i] = g_y[j]; zs[i] = g_z[j];
    }
    ull xp[8], yp[8], zp[8];
#pragma unroll
    for (int p = 0; p < 8; p++) {
        xp[p] = pk2(xs[2*p], xs[2*p+1]);
        yp[p] = pk2(ys[2*p], ys[2*p+1]);
        zp[p] = pk2(zs[2*p], zs[2*p+1]);
    }
    float dst[16];
#pragma unroll
    for (int i = 0; i < 16; i++) dst[i] = BIGF;

    __shared__ unsigned sb[2][16];
    __shared__ unsigned si[2][16];

    float qx = g_x[base], qy = g_y[base], qz = g_z[base];
    int cur = 0;
    int* repb = rep + b * K_;

    for (int k = 0; k < K_; k++) {
        if (t == 0) repb[k] = cur;

        const ull nqx = pk2(-qx, -qx), nqy = pk2(-qy, -qy), nqz = pk2(-qz, -qz);
        float bv = -1.0f;
#pragma unroll
        for (int p = 0; p < 8; p++) {
            ull dx, dy, dz, s;
            ADD2(dx, xp[p], nqx);
            ADD2(dy, yp[p], nqy);
            ADD2(dz, zp[p], nqz);
            MUL2(dx, dx, dx);
            MUL2(dy, dy, dy);
            MUL2(dz, dz, dz);
            ADD2(s, dx, dy);
            ADD2(s, s, dz);
            float n0 = fminf(dst[2*p],   plo(s)); dst[2*p]   = n0;
            float n1 = fminf(dst[2*p+1], phi(s)); dst[2*p+1] = n1;
            bv = fmaxf(bv, fmaxf(n0, n1));
        }

        // warp argmax: max bits; matching lane(s) recover first-index by scan
        const unsigned mybits = __float_as_uint(bv);
        const unsigned mh = __reduce_max_sync(0xffffffffu, mybits);
        unsigned cnd = 0xffffffffu;
        if (mybits == mh) {
            int fi = 0;
#pragma unroll
            for (int i = 15; i >= 0; i--)
                if (__float_as_uint(dst[i]) == mybits) fi = i;   // smallest i wins
            cnd = (unsigned)(t + fi * 512);
        }
        const unsigned mi = __reduce_min_sync(0xffffffffu, cnd);

        const int par = k & 1;
        if (lane == 0) { sb[par][w] = mh; si[par][w] = mi; }
        __syncthreads();

        // all warps redundantly reduce the 16 per-warp candidates
        unsigned v  = (lane < 16) ? sb[par][lane] : 0u;
        unsigned i2 = (lane < 16) ? si[par][lane] : 0xffffffffu;
        unsigned Mh = __reduce_max_sync(0xffffffffu, v);
        unsigned c2 = (v == Mh) ? i2 : 0xffffffffu;
        unsigned Mi = __reduce_min_sync(0xffffffffu, c2);
        cur = (int)Mi;

        // broadcast-load winner coords (same address all lanes; L1 hit)
        qx = g_x[base + cur]; qy = g_y[base + cur]; qz = g_z[base + cur];
    }
}

// ---------------------------------------------------------------------------
// Kernel 2: gather centers (all 6 channels) into the output.
// ---------------------------------------------------------------------------
__global__ void center_kernel(const float* __restrict__ pc,
                              const int* __restrict__ rep,
                              float* __restrict__ out)
{
    int i = blockIdx.x * blockDim.x + threadIdx.x;
    if (i >= CENTER_ELEMS) return;
    int c  = i % C_;
    int bg = i / C_;
    int b  = bg >> 9;
    int g  = bg & (K_ - 1);
    int j  = rep[b * K_ + g];
    out[CENTER_OFF + i] = pc[((size_t)b * N_ + j) * C_ + c];
}

// ---------------------------------------------------------------------------
// kNN key: lexicographic u64 (monotone-float-bits(d2) << 32) | idx.
// Matches lax.top_k(-d2) exact order incl. first-index ties.
// ---------------------------------------------------------------------------
__device__ __forceinline__ ull mkkey(float d2, int j)
{
    int bb = __float_as_int(d2);
    unsigned u = (unsigned)bb ^ ((unsigned)(bb >> 31) | 0x80000000u);
    return ((ull)u << 32) | (unsigned)j;
}

// Scalar reference distance (used only in rare refill rescans).
// Bit-identical to the packed path: rn(-2q*p chain) == -2*dot exactly
// (power-of-2 scaling commutes with rounding).
__device__ __forceinline__ ull dist_key(float px, float py, float pz, float tt,
                                        float qx, float qy, float qz, float qq, int j)
{
    float dot = __fmaf_rn(qz, pz, __fmaf_rn(qy, py, __fmul_rn(qx, px)));
    float d2  = __fadd_rn(__fsub_rn(qq, __fmul_rn(2.0f, dot)), tt);
    return mkkey(d2, j);
}

// ---------------------------------------------------------------------------
// Kernel 3: kNN. 128-thread CTA handles GC=4 centers (warp w <-> center w).
// Points staged through smem in 512-pt chunks; distances computed packed
// (2 points per f32x2 op chain): d2 = (qq + fma-chain(-2q, p)) + tt, exactly
// equal to the reference (qq - 2*dot) + tt. Each thread keeps exact top-2 u64
// keys per center over its 64-point stream (j = m*128 + t). Selection: 32
// redux-min rounds per warp over the 256 candidates; exact gmem-rescan refill
// (min key > last extracted) when a thread's both candidates are consumed.
// ---------------------------------------------------------------------------
#define GC     4
#define CHUNK  512

__global__ __launch_bounds__(128)
void knn_kernel(const float* __restrict__ pc, float* __restrict__ out)
{
    __shared__ __align__(16) float scx[CHUNK];
    __shared__ __align__(16) float scy[CHUNK];
    __shared__ __align__(16) float scz[CHUNK];
    __shared__ __align__(16) float sct[CHUNK];
    __shared__ ull   cands[GC][128][2];
    __shared__ float scq[GC][3];
    __shared__ float sqq[GC];

    const int t = threadIdx.x, lane = t & 31, w = t >> 5;
    const int blk = blockIdx.x;
    const int b = blk >> 7;                 // 128 CTAs per batch (512/GC)
    const int cen0 = (blk & 127) * GC;
    const int bbase = b * N_;

    if (t < GC) {
        int gcen = b * K_ + cen0 + t;
        const float* cp = out + CENTER_OFF + (size_t)gcen * C_;
        float qx = cp[0], qy = cp[1], qz = cp[2];
        scq[t][0] = qx; scq[t][1] = qy; scq[t][2] = qz;
        sqq[t] = __fadd_rn(__fadd_rn(__fmul_rn(qx, qx), __fmul_rn(qy, qy)),
                           __fmul_rn(qz, qz));
    }
    __syncthreads();

    // packed per-center constants: -2*q (exact) and qq
    ull nqx2[GC], nqy2[GC], nqz2[GC], qq2[GC];
#pragma unroll
    for (int c = 0; c < GC; c++) {
        float mx = __fmul_rn(-2.0f, scq[c][0]);
        float my = __fmul_rn(-2.0f, scq[c][1]);
        float mz = __fmul_rn(-2.0f, scq[c][2]);
        nqx2[c] = pk2(mx, mx); nqy2[c] = pk2(my, my); nqz2[c] = pk2(mz, mz);
        qq2[c]  = pk2(sqq[c], sqq[c]);
    }

    ull c0[GC], c1[GC];
#pragma unroll
    for (int c = 0; c < GC; c++) { c0[c] = ~0ull; c1[c] = ~0ull; }

    for (int ch = 0; ch < N_ / CHUNK; ch++) {
        ((float4*)scx)[t] = ((const float4*)(g_x  + bbase + ch * CHUNK))[t];
        ((float4*)scy)[t] = ((const float4*)(g_y  + bbase + ch * CHUNK))[t];
        ((float4*)scz)[t] = ((const float4*)(g_z  + bbase + ch * CHUNK))[t];
        ((float4*)sct)[t] = ((const float4*)(g_tt + bbase + ch * CHUNK))[t];
        __syncthreads();
#pragma unroll
        for (int h = 0; h < 2; h++) {          // two point-pairs per thread
            int jj = h * 256 + t;
            ull px2 = pk2(scx[jj], scx[jj + 128]);
            ull py2 = pk2(scy[jj], scy[jj + 128]);
            ull pz2 = pk2(scz[jj], scz[jj + 128]);
            ull tt2 = pk2(sct[jj], sct[jj + 128]);
            int ja = ch * CHUNK + jj, jb = ja + 128;
#pragma unroll
            for (int c = 0; c < GC; c++) {
                ull nd, d;
                MUL2(nd, nqx2[c], px2);
                FMA2(nd, nqy2[c], py2, nd);
                FMA2(nd, nqz2[c], pz2, nd);    // nd = -2*dot (exact)
                ADD2(d, qq2[c], nd);           // qq - 2*dot
                ADD2(d, d, tt2);               // + tt
                ull ka = mkkey(plo(d), ja);
                if (ka < c1[c]) {
                    if (ka < c0[c]) { c1[c] = c0[c]; c0[c] = ka; }
                    else            { c1[c] = ka; }
                }
                ull kb = mkkey(phi(d), jb);
                if (kb < c1[c]) {
                    if (kb < c0[c]) { c1[c] = c0[c]; c0[c] = kb; }
                    else            { c1[c] = kb; }
                }
            }
        }
        __syncthreads();
    }

#pragma unroll
    for (int c = 0; c < GC; c++) { cands[c][t][0] = c0[c]; cands[c][t][1] = c1[c]; }
    __syncthreads();

    // ---- selection: warp w -> center w; lane owns threads lane*4 + o ----
    const float qx = scq[w][0], qy = scq[w][1], qz = scq[w][2], qq = sqq[w];

    ull fr[GC];
    unsigned stmask = 0;                       // bit o: second candidate consumed
#pragma unroll
    for (int o = 0; o < GC; o++) fr[o] = cands[w][lane * 4 + o][0];

    int selidx = 0;
    for (int r = 0; r < GS_; r++) {
        ull lm = fr[0]; int ow = 0;
#pragma unroll
        for (int o = 1; o < GC; o++) if (fr[o] < lm) { lm = fr[o]; ow = o; }

        unsigned hi  = (unsigned)(lm >> 32);
        unsigned mh  = __reduce_min_sync(0xffffffffu, hi);
        unsigned cnd = (hi == mh) ? (unsigned)lm : 0xffffffffu;
        unsigned mi  = __reduce_min_sync(0xffffffffu, cnd);
        if (lane == r) selidx = (int)mi;

        if (hi == mh && (unsigned)lm == mi) {  // this lane owned the winner
            const int T = lane * 4 + ow;
            ull nv;
            if (!((stmask >> ow) & 1u)) {
                nv = cands[w][T][1];
                stmask |= 1u << ow;
            } else {
                // exact refill: min key strictly greater than last extracted
                nv = ~0ull;
                const ull th = lm;
#pragma unroll 4
                for (int m = 0; m < 64; m++) {
                    int j2 = m * 128 + T;
                    ull key = dist_key(g_x[bbase + j2], g_y[bbase + j2],
                                       g_z[bbase + j2], g_tt[bbase + j2],
                                       qx, qy, qz, qq, j2);
                    if (key > th && key < nv) nv = key;
                }
            }
#pragma unroll
            for (int o = 0; o < GC; o++) if (o == ow) fr[o] = nv;
        }
    }

    // ---- output: lane L holds rank-L neighbor for center w ----
    const int gcen = b * K_ + cen0 + w;
    const int j = selidx;
    float px = g_x[bbase + j], py = g_y[bbase + j], pz = g_z[bbase + j];
    const float* pf = pc + ((size_t)(bbase + j)) * C_;
    float* o6 = out + ((size_t)gcen * GS_ + lane) * C_;
    o6[0] = __fsub_rn(px, qx);
    o6[1] = __fsub_rn(py, qy);
    o6[2] = __fsub_rn(pz, qz);
    o6[3] = pf[3];
    o6[4] = pf[4];
    o6[5] = pf[5];
    out[NN_OFF + (size_t)gcen * GS_ + lane] = (float)j;
}

// ---------------------------------------------------------------------------
extern "C" void kernel_launch(void* const* d_in, const int* in_sizes, int n_in,
                              void* d_out, int out_size)
{
    const float* pc = (const float*)d_in[0];
    float* out = (float*)d_out;

    int* rep = nullptr;
    cudaGetSymbolAddress((void**)&rep, g_rep);

    prep_kernel<<<(B_ * N_ + 255) / 256, 256>>>(pc);
    fps_kernel<<<B_, 512>>>(rep);
    center_kernel<<<(CENTER_ELEMS + 255) / 256, 256>>>(pc, rep, out);
    knn_kernel<<<B_ * K_ / GC, 128>>>(pc, out);
}